// round 12
// baseline (speedup 1.0000x reference)
#include <cuda_runtime.h>
#include <cuda_bf16.h>
#include <cstdint>

// Problem constants
#define B_   64
#define L_   4096
#define KD_  128
#define H_   4
#define OUT_ 256

#define CHUNKS 16                // L-chunks per batch (pass 1)
#define WARPS  4                 // warps per block in pass 1 (128 threads)
#define ROWS_PER_WARP (L_ / CHUNKS / WARPS)   // 64 rows per warp
#define NBLK1 (B_ * CHUNKS)      // 1024

typedef unsigned long long u64;

// Deterministic scratch (no device allocation allowed)
__device__ float g_pacc[NBLK1][KD_ * H_];   // 1024 x 512 f32 = 2 MB
__device__ float g_pZ[NBLK1][H_];
__device__ float g_pooled[B_][KD_ * H_];    // normalized pooled vectors

__device__ __forceinline__ float warp_sum32(float v) {
#pragma unroll
    for (int off = 16; off >= 1; off >>= 1)
        v += __shfl_xor_sync(0xffffffffu, v, off);
    return v;
}

#define PACK2(d, lo, hi)   asm("mov.b64 %0, {%1, %2};" : "=l"(d) : "f"(lo), "f"(hi))
#define UNPACK2(lo, hi, s) asm("mov.b64 {%0, %1}, %2;" : "=f"(lo), "=f"(hi) : "l"(s))
#define FMA2(d, a, b)      asm("fma.rn.f32x2 %0, %1, %2, %0;" : "+l"(d) : "l"(a), "l"(b))

// ---------------------------------------------------------------------------
// Pass 1.
//  * Row-list compaction: each warp writes its live row indices (ballot +
//    popc rank) into smem ONCE; the main loop is a flat fixed-stride loop —
//    no per-iteration bitmap extraction, no data-dependent branches.
//  * 8 live rows per iteration; 8 rows x 4 heads = 32 scores reduced by ONE
//    5-level 32-value butterfly transpose-reduce (R4-proven: lane l ends with
//    the full score of (row l>>2, head l&3)); ONE __expf per lane per 8 rows.
//  * x rows staged to per-warp smem during the dot (own-lane addresses ->
//    program-ordered, no sync needed); accumulate re-reads them.
//  * Weights stored duplicated as (e,e) u64 -> accumulate is 8 FFMA2 + 2
//    packs + 2 LDS.128 per row (vs 16 FFMA + broadcast).
//  * exp(-1e9)==0 in fp32 => skipping masked rows is exact; |score|<~4 => no
//    max subtraction needed.
// ---------------------------------------------------------------------------
__global__ void __launch_bounds__(128, 8)
pool_pass1(const float* __restrict__ x,
           const int* __restrict__ mask,   // bool coerced to int32 by harness
           const float* __restrict__ q)
{
    const int blk  = blockIdx.x;
    const int b    = blk / CHUNKS;
    const int c    = blk % CHUNKS;
    const int w    = threadIdx.x >> 5;
    const int lane = threadIdx.x & 31;

    __shared__ float4 qS4[H_][32];                       // 2 KB
    __shared__ __align__(16) char uS[WARPS][8 * 32 * 16];// 16 KB: xS, then sAcc
    __shared__ __align__(16) u64  wdupS[WARPS][2][32];   // 2 KB, double-buffered
    __shared__ int   rowsS[WARPS][ROWS_PER_WARP + 8];    // live row lists
    __shared__ float sZ[WARPS][H_];

    float4* xSw = reinterpret_cast<float4*>(uS[w]);      // xS[i*32 + lane]

    // qS4[h][kk] = floats [kk*4, kk*4+4) of head h's query
    {
        const int h = threadIdx.x >> 5, kk = threadIdx.x & 31;
        qS4[h][kk] = *reinterpret_cast<const float4*>(q + h * KD_ + kk * 4);
    }

    // ---- build this warp's live-row list ----
    const int l0 = c * (L_ / CHUNKS) + w * ROWS_PER_WARP;
    const int* mb = mask + (size_t)b * L_ + l0;
    int cnt = 0;
#pragma unroll
    for (int half = 0; half < 2; half++) {
        const unsigned mm = __ballot_sync(0xffffffffu, mb[half * 32 + lane] != 0);
        const int rank = __popc(mm & ((1u << lane) - 1));
        if ((mm >> lane) & 1u) rowsS[w][cnt + rank] = half * 32 + lane;
        cnt += __popc(mm);
    }
    if (lane < 8) rowsS[w][cnt + lane] = 0;   // pad (zero-weighted later)
    __syncthreads();                          // also covers qS4

    // Accumulators: accH[h][jp] = (acc[j=2jp][h], acc[j=2jp+1][h])
    u64 accH[H_][2];
    {
        const float z = 0.0f;
#pragma unroll
        for (int h = 0; h < H_; h++) { PACK2(accH[h][0], z, z); PACK2(accH[h][1], z, z); }
    }
    float zacc = 0.0f;

    const char* baseL = (const char*)(x + (size_t)b * L_ * KD_ + (size_t)l0 * KD_)
                        + lane * 16;

    int pb = 0;
    const float frow = (float)(lane >> 2);
#pragma unroll 1
    for (int base = 0; base < cnt; base += 8) {
        const float keep = (base + (lane >> 2) < cnt) ? 1.0f : 0.0f; (void)frow;

        float v[32];
        // ---- two sub-batches of 4 rows: load, dot, stage ----
#pragma unroll
        for (int s = 0; s < 2; s++) {
            int r[4];
#pragma unroll
            for (int i = 0; i < 4; i++) r[i] = rowsS[w][base + s * 4 + i];
            float4 xv[4];
#pragma unroll
            for (int i = 0; i < 4; i++)
                xv[i] = *reinterpret_cast<const float4*>(baseL + ((unsigned)r[i] << 9));
            const float4 qa = qS4[0][lane], qb = qS4[1][lane];
            const float4 qc = qS4[2][lane], qd = qS4[3][lane];
#pragma unroll
            for (int i = 0; i < 4; i++) {
                const int slot = s * 4 + i;
                v[slot * 4 + 0] = xv[i].x * qa.x + xv[i].y * qa.y + xv[i].z * qa.z + xv[i].w * qa.w;
                v[slot * 4 + 1] = xv[i].x * qb.x + xv[i].y * qb.y + xv[i].z * qb.z + xv[i].w * qb.w;
                v[slot * 4 + 2] = xv[i].x * qc.x + xv[i].y * qc.y + xv[i].z * qc.z + xv[i].w * qc.w;
                v[slot * 4 + 3] = xv[i].x * qd.x + xv[i].y * qd.y + xv[i].z * qd.z + xv[i].w * qd.w;
                xSw[slot * 32 + lane] = xv[i];   // xv dies here (own-lane addr)
            }
        }

        // ---- 32-value butterfly transpose-reduce (R4-proven) ----
        // End: v[0] on lane l == full 32-lane sum of value l = (row l>>2, head l&3)
#pragma unroll
        for (int step = 0; step < 5; step++) {
            const int off    = 16 >> step;
            const int half_n = 16 >> step;
            const bool up = (lane & off) != 0;
#pragma unroll
            for (int i = 0; i < 16; i++) {
                if (i < half_n) {
                    const float send = up ? v[i] : v[i + half_n];
                    const float recv = __shfl_xor_sync(0xffffffffu, send, off);
                    v[i] = (up ? v[i + half_n] : v[i]) + recv;
                }
            }
        }

        // ---- weight + duplicated store (lane == row*4 + head) ----
        const float e = __expf(v[0]) * keep;
        u64 ee; PACK2(ee, e, e);
        wdupS[w][pb][lane] = ee;
        __syncwarp();
        zacc += e;                       // Z[lane&3] partial

        // ---- accumulate 8 rows: 8 FFMA2 + 2 packs + 2 LDS.128 per row ----
#pragma unroll
        for (int i = 0; i < 8; i++) {
            const float4 x4 = xSw[i * 32 + lane];
            const ulonglong2 wd01 = *reinterpret_cast<const ulonglong2*>(&wdupS[w][pb][i * 4]);
            const ulonglong2 wd23 = *reinterpret_cast<const ulonglong2*>(&wdupS[w][pb][i * 4 + 2]);
            u64 x01, x23;
            PACK2(x01, x4.x, x4.y);
            PACK2(x23, x4.z, x4.w);
            FMA2(accH[0][0], x01, wd01.x); FMA2(accH[0][1], x23, wd01.x);
            FMA2(accH[1][0], x01, wd01.y); FMA2(accH[1][1], x23, wd01.y);
            FMA2(accH[2][0], x01, wd23.x); FMA2(accH[2][1], x23, wd23.x);
            FMA2(accH[3][0], x01, wd23.y); FMA2(accH[3][1], x23, wd23.y);
        }
        pb ^= 1;                         // next write targets other buffer
    }

    // Z[h] = sum over lanes with (lane&3)==h -> lanes 0..3 (R4-proven)
    float zz = zacc;
#pragma unroll
    for (int off = 16; off >= 4; off >>= 1)
        zz += __shfl_xor_sync(0xffffffffu, zz, off);

    // ---- epilogue: unpack accH into per-warp region (reusing xS space) ----
    __syncwarp();                        // warp done with its xS reads
    float* sAccW = reinterpret_cast<float*>(uS[w]);
#pragma unroll
    for (int h = 0; h < H_; h++) {
        float a0, a1, a2, a3;
        UNPACK2(a0, a1, accH[h][0]);
        UNPACK2(a2, a3, accH[h][1]);
        sAccW[(lane * 4 + 0) * H_ + h] = a0;
        sAccW[(lane * 4 + 1) * H_ + h] = a1;
        sAccW[(lane * 4 + 2) * H_ + h] = a2;
        sAccW[(lane * 4 + 3) * H_ + h] = a3;
    }
    if (lane < H_) sZ[w][lane] = zz;
    __syncthreads();

    const float* uSf = reinterpret_cast<const float*>(uS);
    for (int idx = threadIdx.x; idx < KD_ * H_; idx += 128) {
        float vv = 0.f;
#pragma unroll
        for (int ww = 0; ww < WARPS; ww++)
            vv += uSf[ww * (8 * 32 * 16 / 4) + idx];
        g_pacc[blk][idx] = vv;
    }
    if (threadIdx.x < H_) {
        float vv = 0.f;
#pragma unroll
        for (int ww = 0; ww < WARPS; ww++) vv += sZ[ww][threadIdx.x];
        g_pZ[blk][threadIdx.x] = vv;
    }
}

// ---------------------------------------------------------------------------
// Pass 2a: combine chunk partials + normalize -> g_pooled[b][*].
// ---------------------------------------------------------------------------
__global__ void __launch_bounds__(512, 2)
pool_combine()
{
    const int b   = blockIdx.x;
    const int tid = threadIdx.x;
    __shared__ float Zs[H_];

    if (tid < H_) {
        float vv = 0.f;
#pragma unroll
        for (int c = 0; c < CHUNKS; c++) vv += g_pZ[b * CHUNKS + c][tid];
        Zs[tid] = vv;
    }
    float vv = 0.f;
#pragma unroll
    for (int c = 0; c < CHUNKS; c++) vv += g_pacc[b * CHUNKS + c][tid];
    __syncthreads();
    g_pooled[b][tid] = vv / Zs[tid & (H_ - 1)];
}

// ---------------------------------------------------------------------------
// Pass 2b: out = relu(pooled @ W^T + b + relu(emb[num])).
// ---------------------------------------------------------------------------
__global__ void __launch_bounds__(256, 4)
pool_gemv(const float* __restrict__ W,
          const float* __restrict__ bias,
          const float* __restrict__ emb,
          const int* __restrict__ num,
          float* __restrict__ out)
{
    const int b    = blockIdx.x >> 3;
    const int og   = blockIdx.x & 7;
    const int tid  = threadIdx.x;
    const int wrp  = tid >> 5;
    const int lane = tid & 31;
    const int o0   = og * 32 + wrp * 4;

    __shared__ float pooled[KD_ * H_];
    for (int idx = tid; idx < (KD_ * H_) / 4; idx += 256)
        reinterpret_cast<float4*>(pooled)[idx] =
            reinterpret_cast<const float4*>(g_pooled[b])[idx];
    __syncthreads();

    float4 pv[4];
#pragma unroll
    for (int qi = 0; qi < 4; qi++)
        pv[qi] = *reinterpret_cast<const float4*>(&pooled[qi * 128 + lane * 4]);

    float a[4];
#pragma unroll
    for (int j = 0; j < 4; j++) {
        const float* Wr = W + (size_t)(o0 + j) * (KD_ * H_);
        float ssum = 0.f;
#pragma unroll
        for (int qi = 0; qi < 4; qi++) {
            const float4 wv = *reinterpret_cast<const float4*>(Wr + qi * 128 + lane * 4);
            ssum = fmaf(wv.x, pv[qi].x, fmaf(wv.y, pv[qi].y,
                   fmaf(wv.z, pv[qi].z, fmaf(wv.w, pv[qi].w, ssum))));
        }
        a[j] = warp_sum32(ssum);
    }

    if (lane == 0) {
        const int nb = num[b];
#pragma unroll
        for (int j = 0; j < 4; j++) {
            const int o = o0 + j;
            float vv = a[j] + bias[o] + fmaxf(emb[(size_t)nb * OUT_ + o], 0.f);
            out[(size_t)b * OUT_ + o] = fmaxf(vv, 0.f);
        }
    }
}

// ---------------------------------------------------------------------------
// Launch.  Inputs (metadata order): x, mask, num, queries, W, b, emb
// ---------------------------------------------------------------------------
extern "C" void kernel_launch(void* const* d_in, const int* in_sizes, int n_in,
                              void* d_out, int out_size)
{
    const float* x    = (const float*)d_in[0];
    const int*   mask = (const int*)d_in[1];     // bool -> int32 on upload
    const int*   num  = (const int*)d_in[2];
    const float* q    = (const float*)d_in[3];
    const float* W    = (const float*)d_in[4];
    const float* bias = (const float*)d_in[5];
    const float* emb  = (const float*)d_in[6];
    float*       out  = (float*)d_out;

    pool_pass1<<<NBLK1, 128>>>(x, mask, q);
    pool_combine<<<B_, 512>>>();
    pool_gemv<<<B_ * 8, 256>>>(W, bias, emb, num, out);
}

// round 13
// speedup vs baseline: 1.4589x; 1.4589x over previous
#include <cuda_runtime.h>
#include <cuda_bf16.h>
#include <cstdint>

// Problem constants
#define B_   64
#define L_   4096
#define KD_  128
#define H_   4
#define OUT_ 256

#define CHUNKS 16                // L-chunks per batch (pass 1)
#define WARPS  4                 // warps per block in pass 1 (128 threads)
#define ROWS_PER_WARP (L_ / CHUNKS / WARPS)   // 64 rows per warp
#define NBLK1 (B_ * CHUNKS)      // 1024

// Deterministic scratch (no device allocation allowed)
__device__ float g_pacc[NBLK1][KD_ * H_];   // 1024 x 512 f32 = 2 MB
__device__ float g_pZ[NBLK1][H_];
__device__ float g_pooled[B_][KD_ * H_];    // normalized pooled vectors

__device__ __forceinline__ float warp_sum32(float v) {
#pragma unroll
    for (int off = 16; off >= 1; off >>= 1)
        v += __shfl_xor_sync(0xffffffffu, v, off);
    return v;
}

__device__ __forceinline__ uint32_t smem_u32(const void* p) {
    uint32_t a;
    asm("{ .reg .u64 t; cvta.to.shared.u64 t, %1; cvt.u32.u64 %0, t; }"
        : "=r"(a) : "l"(p));
    return a;
}

// Volatile LDS.128: guaranteed in-loop (prevents hoisting q back into regs).
__device__ __forceinline__ float4 lds128v(uint32_t addr) {
    float4 r;
    asm volatile("ld.shared.v4.f32 {%0,%1,%2,%3}, [%4];"
                 : "=f"(r.x), "=f"(r.y), "=f"(r.z), "=f"(r.w) : "r"(addr));
    return r;
}

// 8-value butterfly transpose-reduce. In: wv[0..7] per lane. Out: return on
// lane l == full 32-lane sum of value (l & 7). Folds {4,2,1} reduce within
// 8-lane subgroups; shfl(8)+shfl(16) complete all 32 lanes. (R10-proven.)
__device__ __forceinline__ float butterfly8(float wv[8], int lane) {
#pragma unroll
    for (int step = 0; step < 3; step++) {
        const int off = 4 >> step;
        const bool up = (lane & off) != 0;
#pragma unroll
        for (int i = 0; i < 4; i++) {
            if (i < (4 >> step)) {
                const float send = up ? wv[i] : wv[i + (4 >> step)];
                const float recv = __shfl_xor_sync(0xffffffffu, send, off);
                wv[i] = (up ? wv[i + (4 >> step)] : wv[i]) + recv;
            }
        }
    }
    float s = wv[0];
    s += __shfl_xor_sync(0xffffffffu, s, 8);
    s += __shfl_xor_sync(0xffffffffu, s, 16);
    return s;
}

// ---------------------------------------------------------------------------
// Pass 1 = R10 structure (best measured: xv in regs, dual butterfly8, sP
// double-buffer, scalar accumulate) + two targeted changes:
//  1. ROW-LIST COMPACTION: live row indices written once (ballot+popc rank);
//     hot loop is flat fixed-stride — no per-iter ffs/branch chain.
//  2. q IN SMEM, loaded per head-pair via asm-volatile LDS.128 -> 16 regs
//     freed -> natural reg count under the 64 cap, no clamp spills.
// NO x staging through smem (R12's L1=64.6% regression).
// exp(-1e9)==0 in fp32 => skipping masked rows is exact; |score|<~4 => no
// max subtraction needed.
// ---------------------------------------------------------------------------
__global__ void __launch_bounds__(128, 8)
pool_pass1(const float* __restrict__ x,
           const int* __restrict__ mask,   // bool coerced to int32 by harness
           const float* __restrict__ q)
{
    const int blk  = blockIdx.x;
    const int b    = blk / CHUNKS;
    const int c    = blk % CHUNKS;
    const int w    = threadIdx.x >> 5;
    const int lane = threadIdx.x & 31;

    __shared__ float4 qS[H_][32];           // query chunks, lane-strided
    __shared__ float  sP[WARPS][2][16];     // double-buffered weight broadcast
    __shared__ float  sAcc[WARPS][KD_ * H_];
    __shared__ float  sZ[WARPS][H_];
    __shared__ int    rowsS[WARPS][ROWS_PER_WARP + 4];

    // qS[h][lane] = floats [lane*4, lane*4+4) of head h's query (w == h)
    qS[w][lane] = *reinterpret_cast<const float4*>(q + w * KD_ + lane * 4);

    // ---- build this warp's live-row list (once) ----
    const int l0 = c * (L_ / CHUNKS) + w * ROWS_PER_WARP;
    const int* mb = mask + (size_t)b * L_ + l0;
    int cnt = 0;
#pragma unroll
    for (int half = 0; half < 2; half++) {
        const unsigned mm = __ballot_sync(0xffffffffu, mb[half * 32 + lane] != 0);
        const int rank = __popc(mm & ((1u << lane) - 1));
        if ((mm >> lane) & 1u) rowsS[w][cnt + rank] = half * 32 + lane;
        cnt += __popc(mm);
    }
    if (lane < 4) rowsS[w][cnt + lane] = 0;   // pad (zero-weighted later)
    __syncthreads();                          // qS visible to all warps

    float acc[4][H_];
#pragma unroll
    for (int j = 0; j < 4; j++)
#pragma unroll
        for (int h = 0; h < H_; h++) acc[j][h] = 0.0f;
    float zaccA = 0.0f, zaccB = 0.0f;

    const char* baseL = (const char*)(x + (size_t)b * L_ * KD_ + (size_t)l0 * KD_)
                        + lane * 16;
    const uint32_t qAddr = smem_u32(&qS[0][lane]);   // +512*h per head
    const int myrow = (lane & 7) >> 1;

    int pb = 0;
#pragma unroll 1
    for (int base = 0; base < cnt; base += 4) {
        const float keep = (base + myrow < cnt) ? 1.0f : 0.0f;

        int r[4];
#pragma unroll
        for (int i = 0; i < 4; i++) r[i] = rowsS[w][base + i];   // LDS broadcast

        float4 xv[4];
#pragma unroll
        for (int i = 0; i < 4; i++)
            xv[i] = *reinterpret_cast<const float4*>(baseL + ((unsigned)r[i] << 9));

        // ---- batch A: heads 0,1 -> wv[row*2 + hh] ----
        float wv[8];
        {
            const float4 qa = lds128v(qAddr);
            const float4 qb = lds128v(qAddr + 512);
#pragma unroll
            for (int i = 0; i < 4; i++) {
                wv[i * 2 + 0] = xv[i].x * qa.x + xv[i].y * qa.y
                              + xv[i].z * qa.z + xv[i].w * qa.w;
                wv[i * 2 + 1] = xv[i].x * qb.x + xv[i].y * qb.y
                              + xv[i].z * qb.z + xv[i].w * qb.w;
            }
        }
        float eA = __expf(butterfly8(wv, lane)) * keep;

        // ---- batch B: heads 2,3 ----
        {
            const float4 qc = lds128v(qAddr + 1024);
            const float4 qd = lds128v(qAddr + 1536);
#pragma unroll
            for (int i = 0; i < 4; i++) {
                wv[i * 2 + 0] = xv[i].x * qc.x + xv[i].y * qc.y
                              + xv[i].z * qc.z + xv[i].w * qc.w;
                wv[i * 2 + 1] = xv[i].x * qd.x + xv[i].y * qd.y
                              + xv[i].z * qd.z + xv[i].w * qd.w;
            }
        }
        float eB = __expf(butterfly8(wv, lane)) * keep;

        // ---- broadcast weights: lanes 0..7 carry the distinct values ----
        if (lane < 8) {
            const int row = lane >> 1, hh = lane & 1;
            sP[w][pb][row * 4 + hh]     = eA;   // heads 0,1
            sP[w][pb][row * 4 + 2 + hh] = eB;   // heads 2,3
        } else {
            eA = 0.0f; eB = 0.0f;
        }
        __syncwarp();
        zaccA += eA;                    // Z[lane&1]     partial
        zaccB += eB;                    // Z[2+(lane&1)] partial

        // ---- accumulate 4 rows (xv in registers) ----
#pragma unroll
        for (int i = 0; i < 4; i++) {
            const float4 pv = *reinterpret_cast<const float4*>(&sP[w][pb][i * 4]);
            acc[0][0] = fmaf(xv[i].x, pv.x, acc[0][0]);
            acc[0][1] = fmaf(xv[i].x, pv.y, acc[0][1]);
            acc[0][2] = fmaf(xv[i].x, pv.z, acc[0][2]);
            acc[0][3] = fmaf(xv[i].x, pv.w, acc[0][3]);
            acc[1][0] = fmaf(xv[i].y, pv.x, acc[1][0]);
            acc[1][1] = fmaf(xv[i].y, pv.y, acc[1][1]);
            acc[1][2] = fmaf(xv[i].y, pv.z, acc[1][2]);
            acc[1][3] = fmaf(xv[i].y, pv.w, acc[1][3]);
            acc[2][0] = fmaf(xv[i].z, pv.x, acc[2][0]);
            acc[2][1] = fmaf(xv[i].z, pv.y, acc[2][1]);
            acc[2][2] = fmaf(xv[i].z, pv.z, acc[2][2]);
            acc[2][3] = fmaf(xv[i].z, pv.w, acc[2][3]);
            acc[3][0] = fmaf(xv[i].w, pv.x, acc[3][0]);
            acc[3][1] = fmaf(xv[i].w, pv.y, acc[3][1]);
            acc[3][2] = fmaf(xv[i].w, pv.z, acc[3][2]);
            acc[3][3] = fmaf(xv[i].w, pv.w, acc[3][3]);
        }
        pb ^= 1;                       // next iter writes other sP buffer; its
                                       // syncwarp fences reuse of this one.
    }

    // Z reduce: same-parity lanes -> lanes 0,1 hold (Z0,Z1) and (Z2,Z3)
    float zA = zaccA, zB = zaccB;
#pragma unroll
    for (int off = 16; off >= 2; off >>= 1) {
        zA += __shfl_xor_sync(0xffffffffu, zA, off);
        zB += __shfl_xor_sync(0xffffffffu, zB, off);
    }

    // ---- block-level deterministic reduce ----
#pragma unroll
    for (int j = 0; j < 4; j++)
#pragma unroll
        for (int h = 0; h < H_; h++)
            sAcc[w][(lane * 4 + j) * H_ + h] = acc[j][h];   // idx = k*H + h
    if (lane < 2) {
        sZ[w][lane]     = zA;
        sZ[w][2 + lane] = zB;
    }
    __syncthreads();

    for (int idx = threadIdx.x; idx < KD_ * H_; idx += 128) {
        float vv = 0.f;
#pragma unroll
        for (int ww = 0; ww < WARPS; ww++) vv += sAcc[ww][idx];
        g_pacc[blk][idx] = vv;
    }
    if (threadIdx.x < H_) {
        float vv = 0.f;
#pragma unroll
        for (int ww = 0; ww < WARPS; ww++) vv += sZ[ww][threadIdx.x];
        g_pZ[blk][threadIdx.x] = vv;
    }
}

// ---------------------------------------------------------------------------
// Pass 2a: combine chunk partials + normalize -> g_pooled[b][*].
// ---------------------------------------------------------------------------
__global__ void __launch_bounds__(512, 2)
pool_combine()
{
    const int b   = blockIdx.x;
    const int tid = threadIdx.x;
    __shared__ float Zs[H_];

    if (tid < H_) {
        float vv = 0.f;
#pragma unroll
        for (int c = 0; c < CHUNKS; c++) vv += g_pZ[b * CHUNKS + c][tid];
        Zs[tid] = vv;
    }
    float vv = 0.f;
#pragma unroll
    for (int c = 0; c < CHUNKS; c++) vv += g_pacc[b * CHUNKS + c][tid];
    __syncthreads();
    g_pooled[b][tid] = vv / Zs[tid & (H_ - 1)];
}

// ---------------------------------------------------------------------------
// Pass 2b: out = relu(pooled @ W^T + b + relu(emb[num])).
// ---------------------------------------------------------------------------
__global__ void __launch_bounds__(256, 4)
pool_gemv(const float* __restrict__ W,
          const float* __restrict__ bias,
          const float* __restrict__ emb,
          const int* __restrict__ num,
          float* __restrict__ out)
{
    const int b    = blockIdx.x >> 3;
    const int og   = blockIdx.x & 7;
    const int tid  = threadIdx.x;
    const int wrp  = tid >> 5;
    const int lane = tid & 31;
    const int o0   = og * 32 + wrp * 4;

    __shared__ float pooled[KD_ * H_];
    for (int idx = tid; idx < (KD_ * H_) / 4; idx += 256)
        reinterpret_cast<float4*>(pooled)[idx] =
            reinterpret_cast<const float4*>(g_pooled[b])[idx];
    __syncthreads();

    float4 pv[4];
#pragma unroll
    for (int qi = 0; qi < 4; qi++)
        pv[qi] = *reinterpret_cast<const float4*>(&pooled[qi * 128 + lane * 4]);

    float a[4];
#pragma unroll
    for (int j = 0; j < 4; j++) {
        const float* Wr = W + (size_t)(o0 + j) * (KD_ * H_);
        float ssum = 0.f;
#pragma unroll
        for (int qi = 0; qi < 4; qi++) {
            const float4 wv = *reinterpret_cast<const float4*>(Wr + qi * 128 + lane * 4);
            ssum = fmaf(wv.x, pv[qi].x, fmaf(wv.y, pv[qi].y,
                   fmaf(wv.z, pv[qi].z, fmaf(wv.w, pv[qi].w, ssum))));
        }
        a[j] = warp_sum32(ssum);
    }

    if (lane == 0) {
        const int nb = num[b];
#pragma unroll
        for (int j = 0; j < 4; j++) {
            const int o = o0 + j;
            float vv = a[j] + bias[o] + fmaxf(emb[(size_t)nb * OUT_ + o], 0.f);
            out[(size_t)b * OUT_ + o] = fmaxf(vv, 0.f);
        }
    }
}

// ---------------------------------------------------------------------------
// Launch.  Inputs (metadata order): x, mask, num, queries, W, b, emb
// ---------------------------------------------------------------------------
extern "C" void kernel_launch(void* const* d_in, const int* in_sizes, int n_in,
                              void* d_out, int out_size)
{
    const float* x    = (const float*)d_in[0];
    const int*   mask = (const int*)d_in[1];     // bool -> int32 on upload
    const int*   num  = (const int*)d_in[2];
    const float* q    = (const float*)d_in[3];
    const float* W    = (const float*)d_in[4];
    const float* bias = (const float*)d_in[5];
    const float* emb  = (const float*)d_in[6];
    float*       out  = (float*)d_out;

    pool_pass1<<<NBLK1, 128>>>(x, mask, q);
    pool_combine<<<B_, 512>>>();
    pool_gemv<<<B_ * 8, 256>>>(W, bias, emb, num, out);
}